// round 15
// baseline (speedup 1.0000x reference)
#include <cuda_runtime.h>

#define NN 8192
#define INDIM 512
#define HID 50
#define ZD 128
#define NCAT 64
#define EPSV 1e-8f
#define NWORK_MAX (NN/32 + NCAT)
#define NFX2 (NN/64)     // fx blocks (64 rows each)
#define NFZ2 (NN/32)     // fz blocks (32 rows each)

// prep dynamic smem (floats): fx phase2 = 13000; fz = 12928 -> 13000 (52 KB)
#define PREP_SMEM_FLOATS 13000
#define PREP_SMEM_BYTES  (PREP_SMEM_FLOATS*4)

// uneg dynamic smem (floats):
//  phase1: FxsTd [128][68] = 8704 | Wst [32][132] = 4224   (12928)
//  phase2: Us    [32][128] = 4096 | Fs  [128][132] = 16896 (20992)  -> 84 KB
#define UNEG_SMEM_FLOATS 20992
#define UNEG_SMEM_BYTES  (UNEG_SMEM_FLOATS*4)

typedef unsigned long long u64;

// ---------------- scratch ----------------------------------------------------
__device__ float g_fx[NN*ZD];    // natural order
__device__ float g_fz[NN*ZD];    // natural order
__device__ int   g_cnt[NCAT], g_start[NCAT];
__device__ int   g_sorted[NN];
__device__ int   g_work[NWORK_MAX];
__device__ int   g_nwork;

// ---------------- f32x2 helpers ----------------------------------------------
__device__ __forceinline__ u64 dup2(float x){
    u64 r; asm("mov.b64 %0, {%1, %1};" : "=l"(r) : "f"(x)); return r;
}
__device__ __forceinline__ void fma2(u64 &d, u64 a, u64 b){
    asm("fma.rn.f32x2 %0, %1, %2, %0;" : "+l"(d) : "l"(a), "l"(b));
}
__device__ __forceinline__ float2 unpk(u64 v){
    float2 f; asm("mov.b64 {%0, %1}, %2;" : "=f"(f.x), "=f"(f.y) : "l"(v)); return f;
}
__device__ __forceinline__ float softplusf(float v){
    return fmaxf(v, 0.f) + log1pf(__expf(-fabsf(v)));
}

// ---------------- prep: block0 = bucket, fx (64-row), fz (32-row) ------------
__global__ void prep_kernel(const float* __restrict__ x,  const float* __restrict__ W1,
                            const float* __restrict__ b1, const float* __restrict__ W2,
                            const float* __restrict__ b2, const float* __restrict__ z,
                            const float* __restrict__ Wz, const float* __restrict__ bz,
                            const int*   __restrict__ c){
    extern __shared__ __align__(16) float dyn[];
    __shared__ float b1s[64];
    __shared__ float b2s[128];
    __shared__ int   s_cnt[NCAT];
    __shared__ int   s_cursor[NCAT];
    int tid  = threadIdx.x;
    int lane = tid & 31;

    if (blockIdx.x == 0){
        // ================= bucket sort (warp-aggregated atomics) =============
        if (tid < NCAT) s_cnt[tid] = 0;
        __syncthreads();
        for (int i = tid; i < NN; i += 256){
            int cc = min(max(c[i], 0), NCAT - 1);
            unsigned m = __match_any_sync(0xffffffffu, cc);
            if ((m & ((1u << lane) - 1)) == 0) atomicAdd(&s_cnt[cc], __popc(m));
        }
        __syncthreads();
        if (tid == 0){
            int s = 0, w = 0;
            for (int cc = 0; cc < NCAT; cc++){
                s_cursor[cc] = s;
                g_start[cc]  = s;
                int n = s_cnt[cc];
                g_cnt[cc] = n;
                s += n;
                int nt = (n + 31) >> 5;
                for (int t = 0; t < nt; t++) g_work[w++] = (cc << 16) | t;
            }
            g_nwork = w;
        }
        __syncthreads();
        for (int i = tid; i < NN; i += 256){
            int cc = min(max(c[i], 0), NCAT - 1);
            unsigned m = __match_any_sync(0xffffffffu, cc);
            int leader = __ffs(m) - 1;
            int rank   = __popc(m & ((1u << lane) - 1));
            int base   = 0;
            if (lane == leader) base = atomicAdd(&s_cursor[cc], __popc(m));
            base = __shfl_sync(0xffffffffu, base, leader);
            g_sorted[base + rank] = i;
        }
    } else if (blockIdx.x <= NFX2){
        // ===== fx = relu(x@W1+b1)@W2+b2, 64 rows, transposed-A + dup-B =======
        float* AT   = dyn;            // [32][68] in k-major: 2176
        float* Bsd  = dyn + 2176;     // [32][132] dup cols: 4224
        float* HsTd = dyn;            // [50][132] dup rows: 6600
        float* W2s  = dyn + 6600;     // [50][128]: 6400

        int row0 = (blockIdx.x - 1) * 64;
        if (tid < 64)  b1s[tid] = (tid < HID) ? b1[tid] : 0.f;
        if (tid < 128) b2s[tid] = b2[tid];

        float4 w2r[7];
        #pragma unroll
        for (int i = 0; i < 7; i++){
            int q = tid + 256*i;
            if (q < 1600) w2r[i] = *(const float4*)&W2[q*4];
        }

        float4 pa[2];
        #pragma unroll
        for (int i = 0; i < 2; i++){
            int s = tid + 256*i;
            pa[i] = *(const float4*)&x[(size_t)(row0 + (s >> 3))*INDIM + (s & 7)*4];
        }
        float pb[8];
        #pragma unroll
        for (int i = 0; i < 8; i++){
            int e = tid + 256*i;
            int k = e >> 6, j = e & 63;
            pb[i] = (j < HID) ? W1[(size_t)k*HID + j] : 0.f;
        }

        int r0 = (tid >> 5) * 8;     // warp-uniform rows r0..r0+7
        int c0 = (tid & 31) * 2;     // lane cols c0, c0+1
        u64 acc[4][2] = {};          // [rowpair][col j]

        for (int t = 0; t < 16; t++){
            __syncthreads();
            #pragma unroll
            for (int i = 0; i < 2; i++){
                int s = tid + 256*i;
                int r = s >> 3, kq = s & 7;
                float4 v = pa[i];
                AT[(kq*4+0)*68 + r] = v.x;
                AT[(kq*4+1)*68 + r] = v.y;
                AT[(kq*4+2)*68 + r] = v.z;
                AT[(kq*4+3)*68 + r] = v.w;
            }
            #pragma unroll
            for (int i = 0; i < 8; i++){
                int e = tid + 256*i;
                int k = e >> 6, j = e & 63;
                Bsd[k*132 + 2*j]     = pb[i];
                Bsd[k*132 + 2*j + 1] = pb[i];
            }
            __syncthreads();
            if (t < 15){
                int k0 = (t+1)*32;
                #pragma unroll
                for (int i = 0; i < 2; i++){
                    int s = tid + 256*i;
                    pa[i] = *(const float4*)&x[(size_t)(row0 + (s >> 3))*INDIM + k0 + (s & 7)*4];
                }
                #pragma unroll
                for (int i = 0; i < 8; i++){
                    int e = tid + 256*i;
                    int k = e >> 6, j = e & 63;
                    pb[i] = (j < HID) ? W1[(size_t)(k0 + k)*HID + j] : 0.f;
                }
            }
            #pragma unroll
            for (int k = 0; k < 32; k++){
                ulonglong2 a03 = *(const ulonglong2*)&AT[k*68 + r0];
                ulonglong2 a47 = *(const ulonglong2*)&AT[k*68 + r0 + 4];
                ulonglong2 bd  = *(const ulonglong2*)&Bsd[k*132 + 2*c0];
                fma2(acc[0][0], a03.x, bd.x); fma2(acc[0][1], a03.x, bd.y);
                fma2(acc[1][0], a03.y, bd.x); fma2(acc[1][1], a03.y, bd.y);
                fma2(acc[2][0], a47.x, bd.x); fma2(acc[2][1], a47.x, bd.y);
                fma2(acc[3][0], a47.y, bd.x); fma2(acc[3][1], a47.y, bd.y);
            }
        }
        __syncthreads();

        #pragma unroll
        for (int p = 0; p < 4; p++){
            #pragma unroll
            for (int j = 0; j < 2; j++){
                int cc = c0 + j;
                if (cc < HID){
                    float2 v = unpk(acc[p][j]);
                    float h0 = fmaxf(v.x + b1s[cc], 0.f);
                    float h1 = fmaxf(v.y + b1s[cc], 0.f);
                    int rA = r0 + 2*p;
                    HsTd[cc*132 + 2*rA]     = h0;
                    HsTd[cc*132 + 2*rA + 1] = h0;
                    HsTd[cc*132 + 2*rA + 2] = h1;
                    HsTd[cc*132 + 2*rA + 3] = h1;
                }
            }
        }
        #pragma unroll
        for (int i = 0; i < 7; i++){
            int q = tid + 256*i;
            if (q < 1600) *(float4*)&W2s[q*4] = w2r[i];
        }
        __syncthreads();

        {
            int c2 = (tid & 31) * 4;
            u64 a2[8][2] = {};
            #pragma unroll
            for (int h = 0; h < HID; h++){
                const float* hp = &HsTd[h*132 + 2*r0];
                ulonglong2 A0 = *(const ulonglong2*)hp;
                ulonglong2 A1 = *(const ulonglong2*)(hp + 4);
                ulonglong2 A2 = *(const ulonglong2*)(hp + 8);
                ulonglong2 A3 = *(const ulonglong2*)(hp + 12);
                ulonglong2 B  = *(const ulonglong2*)&W2s[h*128 + c2];
                fma2(a2[0][0], A0.x, B.x); fma2(a2[0][1], A0.x, B.y);
                fma2(a2[1][0], A0.y, B.x); fma2(a2[1][1], A0.y, B.y);
                fma2(a2[2][0], A1.x, B.x); fma2(a2[2][1], A1.x, B.y);
                fma2(a2[3][0], A1.y, B.x); fma2(a2[3][1], A1.y, B.y);
                fma2(a2[4][0], A2.x, B.x); fma2(a2[4][1], A2.x, B.y);
                fma2(a2[5][0], A2.y, B.x); fma2(a2[5][1], A2.y, B.y);
                fma2(a2[6][0], A3.x, B.x); fma2(a2[6][1], A3.x, B.y);
                fma2(a2[7][0], A3.y, B.x); fma2(a2[7][1], A3.y, B.y);
            }
            #pragma unroll
            for (int i = 0; i < 8; i++){
                float2 p0 = unpk(a2[i][0]);
                float2 p1 = unpk(a2[i][1]);
                float4 v = make_float4(p0.x + b2s[c2], p0.y + b2s[c2+1],
                                       p1.x + b2s[c2+2], p1.y + b2s[c2+3]);
                *(float4*)&g_fx[(size_t)(row0 + r0 + i)*ZD + c2] = v;
            }
        }
    } else {
        // ===== fz = z@Wz+bz, 32 rows, dup-A + pipelined 32-k Wz chunks =======
        float* zTd = dyn;            // [128][68] = 8704
        float* Wzt = dyn + 8704;     // [32][132] = 4224

        int row0 = (blockIdx.x - 1 - NFX2) * 32;

        // stage z tile transposed+dup: 1024 float4 slots (4/thread)
        #pragma unroll
        for (int i = 0; i < 4; i++){
            int s = tid + 256*i;
            int r = s >> 5, kq = s & 31;
            float4 v = *(const float4*)&z[(size_t)(row0 + r)*ZD + kq*4];
            zTd[(kq*4+0)*68 + 2*r] = v.x; zTd[(kq*4+0)*68 + 2*r + 1] = v.x;
            zTd[(kq*4+1)*68 + 2*r] = v.y; zTd[(kq*4+1)*68 + 2*r + 1] = v.y;
            zTd[(kq*4+2)*68 + 2*r] = v.z; zTd[(kq*4+2)*68 + 2*r + 1] = v.z;
            zTd[(kq*4+3)*68 + 2*r] = v.w; zTd[(kq*4+3)*68 + 2*r + 1] = v.w;
        }

        float4 pw[4];
        #pragma unroll
        for (int i = 0; i < 4; i++){
            int q = tid + 256*i;
            pw[i] = *(const float4*)&Wz[(size_t)(q >> 5)*ZD + (q & 31)*4];
        }

        int rg = (tid >> 5) * 4;     // warp-uniform rows rg..rg+3
        int cg = (tid & 31) * 4;
        u64 acc[4][2] = {};          // [row][colpair]

        for (int kt = 0; kt < ZD; kt += 32){
            __syncthreads();                     // zTd staged (1st) / Wzt consumers done
            #pragma unroll
            for (int i = 0; i < 4; i++){
                int q = tid + 256*i;
                *(float4*)&Wzt[(q >> 5)*132 + (q & 31)*4] = pw[i];
            }
            __syncthreads();
            if (kt < ZD - 32){
                #pragma unroll
                for (int i = 0; i < 4; i++){
                    int q = tid + 256*i;
                    pw[i] = *(const float4*)&Wz[(size_t)(kt + 32 + (q >> 5))*ZD + (q & 31)*4];
                }
            }
            #pragma unroll
            for (int k = 0; k < 32; k++){
                const float* ap = &zTd[(kt+k)*68 + 2*rg];
                ulonglong2 a01 = *(const ulonglong2*)ap;
                ulonglong2 a23 = *(const ulonglong2*)(ap + 4);
                ulonglong2 bb  = *(const ulonglong2*)&Wzt[k*132 + cg];
                fma2(acc[0][0], a01.x, bb.x); fma2(acc[0][1], a01.x, bb.y);
                fma2(acc[1][0], a01.y, bb.x); fma2(acc[1][1], a01.y, bb.y);
                fma2(acc[2][0], a23.x, bb.x); fma2(acc[2][1], a23.x, bb.y);
                fma2(acc[3][0], a23.y, bb.x); fma2(acc[3][1], a23.y, bb.y);
            }
        }

        float4 bzv = *(const float4*)&bz[cg];
        #pragma unroll
        for (int i = 0; i < 4; i++){
            float2 p0 = unpk(acc[i][0]);
            float2 p1 = unpk(acc[i][1]);
            float4 v = make_float4(p0.x + bzv.x, p0.y + bzv.y,
                                   p1.x + bzv.z, p1.y + bzv.w);
            *(float4*)&g_fz[(size_t)(row0 + rg + i)*ZD + cg] = v;
        }
    }
}

// ---------------- fused u + neg + output, 128-wide j-tiles -------------------
__global__ void __launch_bounds__(256)
uneg_kernel(const float* __restrict__ Ws, float* __restrict__ out){
    extern __shared__ __align__(16) float dyn[];
    __shared__ float Ts[32];
    __shared__ int   gidx[32];
    float* FxsTd = dyn;          // [128][68]
    float* Wst   = dyn + 8704;   // [32][132]
    float* Us    = dyn;          // [32][128]
    float* Fs    = dyn + 4096;   // [128][132]

    int w = blockIdx.x;
    if (w >= g_nwork) return;
    int item  = g_work[w];
    int cat   = item >> 16, tile = item & 0xffff;
    int start = g_start[cat], cnt = g_cnt[cat];
    int i0    = tile * 32;
    int ni    = min(32, cnt - i0);
    int tid   = threadIdx.x;

    if (tid < 32) gidx[tid] = (tid < ni) ? g_sorted[start + i0 + tid] : 0;

    // stage fx tile transposed + DUPLICATED: FxsTd[k][2r] = FxsTd[k][2r+1]
    {
        int r = tid & 31, kg = tid >> 5;
        int gi = 0; bool act = (r < ni);
        if (act) gi = g_sorted[start + i0 + r];
        const float4* src = (const float4*)&g_fx[(size_t)gi*ZD + kg*16];
        #pragma unroll
        for (int q = 0; q < 4; q++){
            float4 v = act ? src[q] : make_float4(0.f,0.f,0.f,0.f);
            int kb = kg*16 + q*4;
            FxsTd[(kb+0)*68 + 2*r] = v.x; FxsTd[(kb+0)*68 + 2*r + 1] = v.x;
            FxsTd[(kb+1)*68 + 2*r] = v.y; FxsTd[(kb+1)*68 + 2*r + 1] = v.y;
            FxsTd[(kb+2)*68 + 2*r] = v.z; FxsTd[(kb+2)*68 + 2*r + 1] = v.z;
            FxsTd[(kb+3)*68 + 2*r] = v.w; FxsTd[(kb+3)*68 + 2*r + 1] = v.w;
        }
    }

    const float* Wc = Ws + (size_t)cat*ZD*ZD;
    float4 pw[4];
    #pragma unroll
    for (int i = 0; i < 4; i++){
        int q = tid + 256*i;
        pw[i] = *(const float4*)&Wc[(size_t)(q >> 5)*ZD + (q & 31)*4];
    }

    int r0 = (tid >> 5) * 4;     // warp-uniform row group
    int c0 = (tid & 31) * 4;
    u64 acc2[4][2] = {};

    for (int kt = 0; kt < ZD; kt += 32){
        __syncthreads();                          // FxsTd staged (1st) / Wst consumers done
        #pragma unroll
        for (int i = 0; i < 4; i++){
            int q = tid + 256*i;
            *(float4*)&Wst[(q >> 5)*132 + (q & 31)*4] = pw[i];
        }
        __syncthreads();
        if (kt < ZD - 32){
            #pragma unroll
            for (int i = 0; i < 4; i++){
                int q = tid + 256*i;
                pw[i] = *(const float4*)&Wc[(size_t)(kt + 32 + (q >> 5))*ZD + (q & 31)*4];
            }
        }
        #pragma unroll
        for (int k = 0; k < 32; k++){
            const float* ap = &FxsTd[(kt+k)*68 + 2*r0];
            ulonglong2 a01 = *(const ulonglong2*)ap;
            ulonglong2 a23 = *(const ulonglong2*)(ap + 4);
            ulonglong2 bb  = *(const ulonglong2*)&Wst[k*132 + c0];
            fma2(acc2[0][0], a01.x, bb.x); fma2(acc2[0][1], a01.x, bb.y);
            fma2(acc2[1][0], a01.y, bb.x); fma2(acc2[1][1], a01.y, bb.y);
            fma2(acc2[2][0], a23.x, bb.x); fma2(acc2[2][1], a23.x, bb.y);
            fma2(acc2[3][0], a23.y, bb.x); fma2(acc2[3][1], a23.y, bb.y);
        }
    }
    __syncthreads();             // phase-1 reads done; safe to overwrite

    // write U tile
    #pragma unroll
    for (int i = 0; i < 4; i++){
        float2 p0 = unpk(acc2[i][0]);
        float2 p1 = unpk(acc2[i][1]);
        *(float4*)&Us[(r0+i)*128 + c0] = make_float4(p0.x, p0.y, p1.x, p1.y);
    }

    // phase 2: 128-wide j-tiles; lane jj covers j = j0+jj, +32, +64, +96
    int jj = tid & 31;
    int ig = tid >> 5;           // warp owns rows ig*4..+3
    float sum[4] = {0.f, 0.f, 0.f, 0.f};

    for (int j0 = 0; j0 < cnt; j0 += 128){
        int nj = min(128, cnt - j0);
        __syncthreads();         // Us visible (1st) / Fs consumers done
        for (int q = tid; q < nj*32; q += 256){
            int r = q >> 5, c4 = q & 31;
            int gj = g_sorted[start + j0 + r];
            *(float4*)&Fs[r*132 + c4*4] = *(const float4*)&g_fz[(size_t)gj*ZD + c4*4];
        }
        __syncthreads();

        u64 a[4][4] = {};        // [j-quarter][row m]
        #pragma unroll 8
        for (int k0 = 0; k0 < ZD; k0 += 4){
            ulonglong2 f0 = *(const ulonglong2*)&Fs[jj*132 + k0];
            ulonglong2 f1 = *(const ulonglong2*)&Fs[(jj+32)*132 + k0];
            ulonglong2 f2 = *(const ulonglong2*)&Fs[(jj+64)*132 + k0];
            ulonglong2 f3 = *(const ulonglong2*)&Fs[(jj+96)*132 + k0];
            #pragma unroll
            for (int m = 0; m < 4; m++){
                ulonglong2 u = *(const ulonglong2*)&Us[(ig*4 + m)*128 + k0]; // bcast
                fma2(a[0][m], u.x, f0.x); fma2(a[0][m], u.y, f0.y);
                fma2(a[1][m], u.x, f1.x); fma2(a[1][m], u.y, f1.y);
                fma2(a[2][m], u.x, f2.x); fma2(a[2][m], u.y, f2.y);
                fma2(a[3][m], u.x, f3.x); fma2(a[3][m], u.y, f3.y);
            }
        }
        #pragma unroll
        for (int m = 0; m < 4; m++){
            float d[4];
            #pragma unroll
            for (int jq = 0; jq < 4; jq++){
                float2 s = unpk(a[jq][m]); d[jq] = s.x + s.y;
            }
            int rr = ig*4 + m;
            int gd = i0 + rr;                      // diagonal j within category
            if (rr < ni && gd >= j0 && gd < j0 + nj && ((gd - j0) & 31) == jj)
                Ts[rr] = softplusf(d[(gd - j0) >> 5]);
            float v = 0.f;
            #pragma unroll
            for (int jq = 0; jq < 4; jq++)
                if (jj + jq*32 < nj) v += softplusf(d[jq]);
            v += __shfl_xor_sync(0xffffffffu, v, 16);
            v += __shfl_xor_sync(0xffffffffu, v, 8);
            v += __shfl_xor_sync(0xffffffffu, v, 4);
            v += __shfl_xor_sync(0xffffffffu, v, 2);
            v += __shfl_xor_sync(0xffffffffu, v, 1);
            sum[m] += v;
        }
    }
    __syncthreads();             // Ts visible

    if (jj == 0){
        float inv = 1.f / (float)cnt;
        #pragma unroll
        for (int m = 0; m < 4; m++){
            int rr = ig*4 + m;
            if (rr < ni)
                out[gidx[rr]] = logf(Ts[rr] + EPSV) - logf(sum[m]*inv + EPSV);
        }
    }
}

// ---------------- launch ----------------------------------------------------
extern "C" void kernel_launch(void* const* d_in, const int* in_sizes, int n_in,
                              void* d_out, int out_size){
    const float* x  = (const float*)d_in[0];
    const int*   c  = (const int*)  d_in[1];
    const float* z  = (const float*)d_in[2];
    const float* W1 = (const float*)d_in[3];
    const float* b1 = (const float*)d_in[4];
    const float* W2 = (const float*)d_in[5];
    const float* b2 = (const float*)d_in[6];
    const float* Wz = (const float*)d_in[7];
    const float* bz = (const float*)d_in[8];
    const float* Ws = (const float*)d_in[9];
    float* out = (float*)d_out;

    cudaFuncSetAttribute(prep_kernel, cudaFuncAttributeMaxDynamicSharedMemorySize,
                         PREP_SMEM_BYTES);
    cudaFuncSetAttribute(uneg_kernel, cudaFuncAttributeMaxDynamicSharedMemorySize,
                         UNEG_SMEM_BYTES);

    prep_kernel <<<1 + NFX2 + NFZ2, 256, PREP_SMEM_BYTES>>>(x, W1, b1, W2, b2, z, Wz, bz, c);
    uneg_kernel <<<NWORK_MAX, 256, UNEG_SMEM_BYTES>>>(Ws, out);
}

// round 16
// speedup vs baseline: 1.0931x; 1.0931x over previous
#include <cuda_runtime.h>

#define NN 8192
#define INDIM 512
#define HID 50
#define ZD 128
#define NCAT 64
#define EPSV 1e-8f
#define NWORK_MAX (NN/32 + NCAT)
#define NFX (NN/32)
#define NFZ (NN/32)

// uneg dynamic smem (floats):
//  phase1: FxsTd [128][68] = 8704 | Wst [32][132] = 4224   (12928)
//  phase2: Us    [32][128] = 4096 | Fs  [128][132] = 16896 (20992) -> 84 KB
#define UNEG_SMEM_FLOATS 20992
#define UNEG_SMEM_BYTES  (UNEG_SMEM_FLOATS*4)

typedef unsigned long long u64;

// ---------------- scratch ----------------------------------------------------
__device__ float g_fx[NN*ZD];    // natural order
__device__ float g_fz[NN*ZD];    // natural order
__device__ int   g_cnt[NCAT], g_start[NCAT];
__device__ int   g_sorted[NN];
__device__ int   g_work[NWORK_MAX];
__device__ int   g_nwork;

// ---------------- f32x2 helpers ----------------------------------------------
__device__ __forceinline__ u64 dup2(float x){
    u64 r; asm("mov.b64 %0, {%1, %1};" : "=l"(r) : "f"(x)); return r;
}
__device__ __forceinline__ void fma2(u64 &d, u64 a, u64 b){
    asm("fma.rn.f32x2 %0, %1, %2, %0;" : "+l"(d) : "l"(a), "l"(b));
}
__device__ __forceinline__ float2 unpk(u64 v){
    float2 f; asm("mov.b64 {%0, %1}, %2;" : "=f"(f.x), "=f"(f.y) : "l"(v)); return f;
}
__device__ __forceinline__ float softplusf(float v){
    return fmaxf(v, 0.f) + log1pf(__expf(-fabsf(v)));
}

// ---------------- prep: block0 = bucket, blocks 1..512 = fx/fz (R12 proven) --
__global__ void prep_kernel(const float* __restrict__ x,  const float* __restrict__ W1,
                            const float* __restrict__ b1, const float* __restrict__ W2,
                            const float* __restrict__ b2, const float* __restrict__ z,
                            const float* __restrict__ Wz, const float* __restrict__ bz,
                            const int*   __restrict__ c){
    __shared__ __align__(16) float sbuf[8064];
    __shared__ float aux128[128];
    __shared__ float aux64[64];
    __shared__ int   s_cnt[NCAT];
    __shared__ int   s_cursor[NCAT];
    int tid  = threadIdx.x;
    int lane = tid & 31;

    if (blockIdx.x == 0){
        if (tid < NCAT) s_cnt[tid] = 0;
        __syncthreads();
        for (int i = tid; i < NN; i += 256){
            int cc = min(max(c[i], 0), NCAT - 1);
            unsigned m = __match_any_sync(0xffffffffu, cc);
            if ((m & ((1u << lane) - 1)) == 0) atomicAdd(&s_cnt[cc], __popc(m));
        }
        __syncthreads();
        if (tid == 0){
            int s = 0, w = 0;
            for (int cc = 0; cc < NCAT; cc++){
                s_cursor[cc] = s;
                g_start[cc]  = s;
                int n = s_cnt[cc];
                g_cnt[cc] = n;
                s += n;
                int nt = (n + 31) >> 5;
                for (int t = 0; t < nt; t++) g_work[w++] = (cc << 16) | t;
            }
            g_nwork = w;
        }
        __syncthreads();
        for (int i = tid; i < NN; i += 256){
            int cc = min(max(c[i], 0), NCAT - 1);
            unsigned m = __match_any_sync(0xffffffffu, cc);
            int leader = __ffs(m) - 1;
            int rank   = __popc(m & ((1u << lane) - 1));
            int base   = 0;
            if (lane == leader) base = atomicAdd(&s_cursor[cc], __popc(m));
            base = __shfl_sync(0xffffffffu, base, leader);
            g_sorted[base + rank] = i;
        }
    } else if (blockIdx.x <= NFX){
        // ===== fx = relu(x@W1+b1)@W2+b2, 32 rows =====
        float* As  = sbuf;            // [32][36]
        float* Bs  = sbuf + 1152;     // [32][64]
        float* Hs  = sbuf;            // [32][52]
        float* W2s = sbuf + 1664;     // [50][128]
        float* b1s = aux64;
        float* b2s = aux128;

        int row0 = (blockIdx.x - 1) * 32;
        if (tid < 64)  b1s[tid] = (tid < HID) ? b1[tid] : 0.f;
        if (tid < 128) b2s[tid] = b2[tid];

        float4 w2r[7];
        #pragma unroll
        for (int i = 0; i < 7; i++){
            int q = tid + 256*i;
            if (q < 1600) w2r[i] = *(const float4*)&W2[q*4];
        }

        int ar = tid >> 3, ac4 = tid & 7;
        float4 pa = *(const float4*)&x[(size_t)(row0 + ar)*INDIM + ac4*4];
        float pb[8];
        #pragma unroll
        for (int i = 0; i < 8; i++){
            int e = tid + 256*i;
            int k = e >> 6, j = e & 63;
            pb[i] = (j < HID) ? W1[(size_t)k*HID + j] : 0.f;
        }

        int rg = (tid >> 4) * 2;
        int cg = (tid & 15) * 4;
        u64 acc2[2][2] = {};

        for (int t = 0; t < 16; t++){
            __syncthreads();
            *(float4*)&As[ar*36 + ac4*4] = pa;
            #pragma unroll
            for (int i = 0; i < 8; i++){
                int e = tid + 256*i;
                Bs[(e >> 6)*64 + (e & 63)] = pb[i];
            }
            __syncthreads();
            if (t < 15){
                int k0 = (t+1)*32;
                pa = *(const float4*)&x[(size_t)(row0 + ar)*INDIM + k0 + ac4*4];
                #pragma unroll
                for (int i = 0; i < 8; i++){
                    int e = tid + 256*i;
                    int k = e >> 6, j = e & 63;
                    pb[i] = (j < HID) ? W1[(size_t)(k0 + k)*HID + j] : 0.f;
                }
            }
            #pragma unroll
            for (int k = 0; k < 32; k++){
                u64 da0 = dup2(As[rg*36 + k]);
                u64 da1 = dup2(As[(rg+1)*36 + k]);
                ulonglong2 bb = *(const ulonglong2*)&Bs[k*64 + cg];
                fma2(acc2[0][0], da0, bb.x); fma2(acc2[0][1], da0, bb.y);
                fma2(acc2[1][0], da1, bb.x); fma2(acc2[1][1], da1, bb.y);
            }
        }
        __syncthreads();

        #pragma unroll
        for (int i = 0; i < 2; i++){
            float2 p0 = unpk(acc2[i][0]);
            float2 p1 = unpk(acc2[i][1]);
            float hv[4] = {p0.x, p0.y, p1.x, p1.y};
            #pragma unroll
            for (int j = 0; j < 4; j++){
                int cc = cg + j;
                if (cc < HID) Hs[(rg+i)*52 + cc] = fmaxf(hv[j] + b1s[cc], 0.f);
            }
        }
        #pragma unroll
        for (int i = 0; i < 7; i++){
            int q = tid + 256*i;
            if (q < 1600) *(float4*)&W2s[q*4] = w2r[i];
        }
        __syncthreads();

        {
            int r0 = (tid >> 5) * 4;
            int c0 = (tid & 31) * 4;
            u64 a2[4][2] = {};
            #pragma unroll
            for (int k = 0; k < HID; k++){
                ulonglong2 bb = *(const ulonglong2*)&W2s[k*128 + c0];
                #pragma unroll
                for (int i = 0; i < 4; i++){
                    u64 da = dup2(Hs[(r0+i)*52 + k]);
                    fma2(a2[i][0], da, bb.x);
                    fma2(a2[i][1], da, bb.y);
                }
            }
            #pragma unroll
            for (int i = 0; i < 4; i++){
                float2 p0 = unpk(a2[i][0]);
                float2 p1 = unpk(a2[i][1]);
                float4 v = make_float4(p0.x + b2s[c0], p0.y + b2s[c0+1],
                                       p1.x + b2s[c0+2], p1.y + b2s[c0+3]);
                *(float4*)&g_fx[(size_t)(row0 + r0 + i)*ZD + c0] = v;
            }
        }
    } else {
        // ===== fz = z@Wz+bz, 32 rows =====
        float* Zs  = sbuf;            // [32][36]
        float* Wzt = sbuf + 1152;     // [32][132]
        float* bzs = aux128;

        int row0 = (blockIdx.x - 1 - NFX) * 32;
        if (tid < 128) bzs[tid] = bz[tid];

        int ar = tid >> 3, ac4 = tid & 7;
        float4 pz = *(const float4*)&z[(size_t)(row0 + ar)*ZD + ac4*4];
        float4 pw[4];
        #pragma unroll
        for (int i = 0; i < 4; i++){
            int q = tid + 256*i;
            pw[i] = *(const float4*)&Wz[(size_t)(q >> 5)*ZD + (q & 31)*4];
        }

        int rg = (tid >> 4) * 2;
        int cg = (tid & 15) * 4;
        u64 acc2[2][4] = {};

        for (int kt = 0; kt < 4; kt++){
            __syncthreads();
            *(float4*)&Zs[ar*36 + ac4*4] = pz;
            #pragma unroll
            for (int i = 0; i < 4; i++){
                int q = tid + 256*i;
                *(float4*)&Wzt[(q >> 5)*132 + (q & 31)*4] = pw[i];
            }
            __syncthreads();
            if (kt < 3){
                int k0 = (kt+1)*32;
                pz = *(const float4*)&z[(size_t)(row0 + ar)*ZD + k0 + ac4*4];
                #pragma unroll
                for (int i = 0; i < 4; i++){
                    int q = tid + 256*i;
                    pw[i] = *(const float4*)&Wz[(size_t)(k0 + (q >> 5))*ZD + (q & 31)*4];
                }
            }
            #pragma unroll
            for (int k = 0; k < 32; k++){
                u64 da0 = dup2(Zs[rg*36 + k]);
                u64 da1 = dup2(Zs[(rg+1)*36 + k]);
                ulonglong2 b0 = *(const ulonglong2*)&Wzt[k*132 + cg];
                ulonglong2 b1 = *(const ulonglong2*)&Wzt[k*132 + cg + 64];
                fma2(acc2[0][0], da0, b0.x); fma2(acc2[0][1], da0, b0.y);
                fma2(acc2[0][2], da0, b1.x); fma2(acc2[0][3], da0, b1.y);
                fma2(acc2[1][0], da1, b0.x); fma2(acc2[1][1], da1, b0.y);
                fma2(acc2[1][2], da1, b1.x); fma2(acc2[1][3], da1, b1.y);
            }
        }

        #pragma unroll
        for (int i = 0; i < 2; i++){
            size_t base = (size_t)(row0 + rg + i)*ZD;
            float2 p0 = unpk(acc2[i][0]), p1 = unpk(acc2[i][1]);
            float2 p2 = unpk(acc2[i][2]), p3 = unpk(acc2[i][3]);
            *(float4*)&g_fz[base + cg] =
                make_float4(p0.x + bzs[cg],   p0.y + bzs[cg+1],
                            p1.x + bzs[cg+2], p1.y + bzs[cg+3]);
            *(float4*)&g_fz[base + cg + 64] =
                make_float4(p2.x + bzs[cg+64], p2.y + bzs[cg+65],
                            p3.x + bzs[cg+66], p3.y + bzs[cg+67]);
        }
    }
}

// ---------------- fused u + neg + output ------------------------------------
// phase1: R12 proven (4 rows x 4 cols / warp, dup-A, pipelined Ws chunks)
// phase2: 8 rows x 2 j per warp, 128-wide Fs tile (crossbar-optimal: 0.5 cyc/FMA2)
__global__ void __launch_bounds__(256)
uneg_kernel(const float* __restrict__ Ws, float* __restrict__ out){
    extern __shared__ __align__(16) float dyn[];
    __shared__ float Ts[32];
    __shared__ int   gidx[32];
    __shared__ float s_part[8][8];
    float* FxsTd = dyn;          // [128][68]
    float* Wst   = dyn + 8704;   // [32][132]
    float* Us    = dyn;          // [32][128]
    float* Fs    = dyn + 4096;   // [128][132]

    int w = blockIdx.x;
    if (w >= g_nwork) return;
    int item  = g_work[w];
    int cat   = item >> 16, tile = item & 0xffff;
    int start = g_start[cat], cnt = g_cnt[cat];
    int i0    = tile * 32;
    int ni    = min(32, cnt - i0);
    int tid   = threadIdx.x;

    if (tid < 32) gidx[tid] = (tid < ni) ? g_sorted[start + i0 + tid] : 0;

    // stage fx tile transposed + DUPLICATED: FxsTd[k][2r] = FxsTd[k][2r+1]
    {
        int r = tid & 31, kg = tid >> 5;
        int gi = 0; bool act = (r < ni);
        if (act) gi = g_sorted[start + i0 + r];
        const float4* src = (const float4*)&g_fx[(size_t)gi*ZD + kg*16];
        #pragma unroll
        for (int q = 0; q < 4; q++){
            float4 v = act ? src[q] : make_float4(0.f,0.f,0.f,0.f);
            int kb = kg*16 + q*4;
            FxsTd[(kb+0)*68 + 2*r] = v.x; FxsTd[(kb+0)*68 + 2*r + 1] = v.x;
            FxsTd[(kb+1)*68 + 2*r] = v.y; FxsTd[(kb+1)*68 + 2*r + 1] = v.y;
            FxsTd[(kb+2)*68 + 2*r] = v.z; FxsTd[(kb+2)*68 + 2*r + 1] = v.z;
            FxsTd[(kb+3)*68 + 2*r] = v.w; FxsTd[(kb+3)*68 + 2*r + 1] = v.w;
        }
    }

    const float* Wc = Ws + (size_t)cat*ZD*ZD;
    float4 pw[4];
    #pragma unroll
    for (int i = 0; i < 4; i++){
        int q = tid + 256*i;
        pw[i] = *(const float4*)&Wc[(size_t)(q >> 5)*ZD + (q & 31)*4];
    }

    int r0 = (tid >> 5) * 4;     // warp-uniform row group
    int c0 = (tid & 31) * 4;
    u64 acc2[4][2] = {};

    for (int kt = 0; kt < ZD; kt += 32){
        __syncthreads();                          // FxsTd staged (1st) / Wst consumers done
        #pragma unroll
        for (int i = 0; i < 4; i++){
            int q = tid + 256*i;
            *(float4*)&Wst[(q >> 5)*132 + (q & 31)*4] = pw[i];
        }
        __syncthreads();
        if (kt < ZD - 32){
            #pragma unroll
            for (int i = 0; i < 4; i++){
                int q = tid + 256*i;
                pw[i] = *(const float4*)&Wc[(size_t)(kt + 32 + (q >> 5))*ZD + (q & 31)*4];
            }
        }
        #pragma unroll
        for (int k = 0; k < 32; k++){
            const float* ap = &FxsTd[(kt+k)*68 + 2*r0];
            ulonglong2 a01 = *(const ulonglong2*)ap;        // dup(r0), dup(r0+1)
            ulonglong2 a23 = *(const ulonglong2*)(ap + 4);  // dup(r0+2), dup(r0+3)
            ulonglong2 bb  = *(const ulonglong2*)&Wst[k*132 + c0];
            fma2(acc2[0][0], a01.x, bb.x); fma2(acc2[0][1], a01.x, bb.y);
            fma2(acc2[1][0], a01.y, bb.x); fma2(acc2[1][1], a01.y, bb.y);
            fma2(acc2[2][0], a23.x, bb.x); fma2(acc2[2][1], a23.x, bb.y);
            fma2(acc2[3][0], a23.y, bb.x); fma2(acc2[3][1], a23.y, bb.y);
        }
    }
    __syncthreads();             // phase-1 reads done; safe to overwrite

    // write U tile (rows >= ni are zeros)
    #pragma unroll
    for (int i = 0; i < 4; i++){
        float2 p0 = unpk(acc2[i][0]);
        float2 p1 = unpk(acc2[i][1]);
        *(float4*)&Us[(r0+i)*128 + c0] = make_float4(p0.x, p0.y, p1.x, p1.y);
    }

    // phase 2: warp wv owns rows (wv&3)*8..+7 and j-quadrant (wv>>2)*64
    int jj    = tid & 31;
    int wv    = tid >> 5;
    int rbase = (wv & 3) * 8;
    int joff  = (wv >> 2) * 64;
    float sum[8] = {0.f,0.f,0.f,0.f,0.f,0.f,0.f,0.f};

    for (int j0 = 0; j0 < cnt; j0 += 128){
        int nj = min(128, cnt - j0);
        __syncthreads();         // Us visible (1st) / Fs consumers done
        for (int q = tid; q < nj*32; q += 256){
            int r = q >> 5, c4 = q & 31;
            int gj = g_sorted[start + j0 + r];
            *(float4*)&Fs[r*132 + c4*4] = *(const float4*)&g_fz[(size_t)gj*ZD + c4*4];
        }
        __syncthreads();

        u64 a[2][8] = {};        // [j-half][row]
        #pragma unroll 8
        for (int k0 = 0; k0 < ZD; k0 += 4){
            ulonglong2 f1 = *(const ulonglong2*)&Fs[(jj + joff)*132 + k0];
            ulonglong2 f2 = *(const ulonglong2*)&Fs[(jj + joff + 32)*132 + k0];
            #pragma unroll
            for (int m = 0; m < 8; m++){
                ulonglong2 u = *(const ulonglong2*)&Us[(rbase + m)*128 + k0]; // bcast
                fma2(a[0][m], u.x, f1.x); fma2(a[0][m], u.y, f1.y);
                fma2(a[1][m], u.x, f2.x); fma2(a[1][m], u.y, f2.y);
            }
        }
        #pragma unroll
        for (int m = 0; m < 8; m++){
            float2 s1 = unpk(a[0][m]); float d1 = s1.x + s1.y;
            float2 s2 = unpk(a[1][m]); float d2 = s2.x + s2.y;
            int rr = rbase + m;
            int dj = i0 + rr - j0;                 // diagonal j within this tile
            if (rr < ni && dj >= 0 && dj < nj &&
                (dj >> 6) == (wv >> 2) && (dj & 31) == jj)
                Ts[rr] = softplusf((dj >> 5) & 1 ? d2 : d1);
            float v = 0.f;
            if (jj + joff      < nj) v += softplusf(d1);
            if (jj + joff + 32 < nj) v += softplusf(d2);
            v += __shfl_xor_sync(0xffffffffu, v, 16);
            v += __shfl_xor_sync(0xffffffffu, v, 8);
            v += __shfl_xor_sync(0xffffffffu, v, 4);
            v += __shfl_xor_sync(0xffffffffu, v, 2);
            v += __shfl_xor_sync(0xffffffffu, v, 1);
            sum[m] += v;
        }
    }

    // combine the two j-quadrant warps per row group
    if (jj == 0){
        #pragma unroll
        for (int m = 0; m < 8; m++) s_part[wv][m] = sum[m];
    }
    __syncthreads();             // s_part + Ts visible

    if (tid < ni){
        float s = s_part[tid >> 3][tid & 7] + s_part[(tid >> 3) + 4][tid & 7];
        out[gidx[tid]] = logf(Ts[tid] + EPSV) - logf(s / (float)cnt + EPSV);
    }
}

// ---------------- launch ----------------------------------------------------
extern "C" void kernel_launch(void* const* d_in, const int* in_sizes, int n_in,
                              void* d_out, int out_size){
    const float* x  = (const float*)d_in[0];
    const int*   c  = (const int*)  d_in[1];
    const float* z  = (const float*)d_in[2];
    const float* W1 = (const float*)d_in[3];
    const float* b1 = (const float*)d_in[4];
    const float* W2 = (const float*)d_in[5];
    const float* b2 = (const float*)d_in[6];
    const float* Wz = (const float*)d_in[7];
    const float* bz = (const float*)d_in[8];
    const float* Ws = (const float*)d_in[9];
    float* out = (float*)d_out;

    cudaFuncSetAttribute(uneg_kernel, cudaFuncAttributeMaxDynamicSharedMemorySize,
                         UNEG_SMEM_BYTES);

    prep_kernel <<<1 + NFX + NFZ, 256>>>(x, W1, b1, W2, b2, z, Wz, bz, c);
    uneg_kernel <<<NWORK_MAX, 256, UNEG_SMEM_BYTES>>>(Ws, out);
}